// round 9
// baseline (speedup 1.0000x reference)
#include <cuda_runtime.h>
#include <string.h>
#include <math.h>

#define NQ 14
#define NL 4
#define NGATES 56
#define STH 256
#define SBLK 8
#define MTH 256
#define MB 8
#define SCAP 20000

// Param-only bucket tables S_m(t) = (sum cos(dTheta), sum sin(dTheta)); worst case 14*8192.
__device__ float2 g_S[14 * 8192];

struct SetupCfg {
    unsigned short mu[NGATES];     // phase parity masks, rows of M^l (tau = I frame)
    unsigned short delta[NQ];      // flip sets: columns of M^-4
    unsigned char  k[NQ];          // popc(delta)
    unsigned char  dbits[NQ][NQ];  // delta bits ascending
    unsigned char  cbits[NQ][NQ];  // complement bits ascending
    int soff[NQ];
};

struct MainCfg {
    unsigned char keff[NQ], klo[NQ], khi[NQ], jtop[NQ];
    unsigned char jb[NQ][NQ];      // free delta bits (ascending), keff of them
    int soff[NQ], ploff[NQ], phoff[NQ];
    int s_total, t_total, stage;
};

__device__ __forceinline__ float2 cmulf(float2 a, float2 b) {
    return make_float2(a.x * b.x - a.y * b.y, a.x * b.y + a.y * b.x);
}

// ---- setup: deterministic per-bucket sums over free bits (no atomics) ----
__global__ void __launch_bounds__(STH)
qsetup(const float* __restrict__ params, SetupCfg c)
{
    __shared__ float th[NGATES];
    __shared__ unsigned short smu[NGATES];
    __shared__ int gl[NGATES];
    __shared__ int ngl_s;
    const int m = blockIdx.x, tid = threadIdx.x;

    if (tid < NGATES) { th[tid] = params[tid]; smu[tid] = c.mu[tid]; }
    if (tid == 0) {
        int n = 0;
        for (int g = 0; g < NGATES; ++g)
            if (__popc((int)(c.mu[g] & c.delta[m])) & 1) gl[n++] = g;
        ngl_s = n;
    }
    __syncthreads();

    const int ngl  = ngl_s;
    const int k    = c.k[m], keff = k - 1;
    const int nt   = 1 << keff, nf = 1 << (14 - k);

    for (int t = blockIdx.y * STH + tid; t < nt; t += SBLK * STH) {
        unsigned base = 0;
        for (int r = 0; r < keff; ++r)
            base |= ((unsigned)(t >> r) & 1u) << c.dbits[m][r];   // top delta bit stays 0
        float cs = 0.f, sn = 0.f;
        for (int f = 0; f < nf; ++f) {
            unsigned p = base;
            for (int r = 0; r < 14 - k; ++r)
                p |= ((unsigned)(f >> r) & 1u) << c.cbits[m][r];
            float ang = 0.f;
            for (int gi = 0; gi < ngl; ++gi) {
                const int g = gl[gi];
                ang += (__popc(p & (unsigned)smu[g]) & 1) ? -th[g] : th[g];
            }
            float s2, c2;
            sincosf(ang, &s2, &c2);
            cs += c2; sn += s2;
        }
        g_S[c.soff[m] + t] = make_float2(cs, sn);
    }
}

// ---- main: per batch element, out_m = (2/2^14) * sum_t Re(P_m(t) * S_m(t)) ----
__global__ void __launch_bounds__(MTH)
qmain(const float* __restrict__ x, float* __restrict__ out, int batch, MainCfg c)
{
    extern __shared__ float2 dyn[];
    float2* Ssm = dyn;
    float2* T   = dyn + (c.stage ? c.s_total : 0);
    __shared__ float2 u[NQ];
    __shared__ float red[MTH / 32][NQ];
    const int tid = threadIdx.x;

    if (c.stage)
        for (int i = tid; i < c.s_total; i += MTH) Ssm[i] = g_S[i];

    #pragma unroll 1
    for (int bi = 0; bi < MB; ++bi) {
        const int b = blockIdx.x * MB + bi;
        if (b >= batch) break;

        if (tid < NQ) {   // u[j] = e^{i x_{13-j}}, j = storage bit
            float s, co;
            sincosf(x[b * NQ + 13 - tid], &s, &co);
            u[tid] = make_float2(co, s);
        }
        __syncthreads();

        // build split phasor tables PL/PH for all m
        #pragma unroll 1
        for (int m = 0; m < NQ; ++m) {
            const int klo = c.klo[m], khi = c.khi[m];
            for (int e = tid; e < (1 << klo); e += MTH) {
                float2 v = make_float2(1.f, 0.f);
                for (int r = 0; r < klo; ++r) {
                    float2 w = u[c.jb[m][r]];
                    if ((e >> r) & 1) w.y = -w.y;
                    v = cmulf(v, w);
                }
                T[c.ploff[m] + e] = v;
            }
            for (int e = tid; e < (1 << khi); e += MTH) {
                float2 v = u[c.jtop[m]];   // fixed top-bit (=0) contributes +x_{jtop}
                for (int r = 0; r < khi; ++r) {
                    float2 w = u[c.jb[m][klo + r]];
                    if ((e >> r) & 1) w.y = -w.y;
                    v = cmulf(v, w);
                }
                T[c.phoff[m] + e] = v;
            }
        }
        __syncthreads();

        float a14[NQ];
        #pragma unroll 1
        for (int m = 0; m < NQ; ++m) {
            const int nt = 1 << c.keff[m], klo = c.klo[m];
            const int so = c.soff[m];
            const float2  pl  = T[c.ploff[m] + (tid & ((1 << klo) - 1))]; // stride 256 >= 2^klo
            const float2* Tph = T + c.phoff[m];
            float a = 0.f;
            for (int t = tid; t < nt; t += MTH) {
                float2 ph = Tph[t >> klo];
                float2 P  = cmulf(pl, ph);
                float2 S  = c.stage ? Ssm[so + t] : g_S[so + t];
                a += P.x * S.x - P.y * S.y;
            }
            a14[m] = a;
        }

        #pragma unroll
        for (int m = 0; m < NQ; ++m)
            #pragma unroll
            for (int o = 16; o; o >>= 1)
                a14[m] += __shfl_down_sync(0xffffffffu, a14[m], o);
        if ((tid & 31) == 0)
            for (int m = 0; m < NQ; ++m) red[tid >> 5][m] = a14[m];
        __syncthreads();
        if (tid < NQ) {
            float tot = 0.f;
            #pragma unroll
            for (int w = 0; w < MTH / 32; ++w) tot += red[w][13 - tid];
            out[b * NQ + tid] = tot * (1.f / 8192.f);   // 2 / 2^14
        }
        __syncthreads();
    }
}

// ================= host side =================
// Conjugated (H-frame) CNOT ring index map, validated in R6/R7.
static unsigned Pp(unsigned v, int q) {
    int cc = 13 - ((q + 1) % NQ);
    int tt = 13 - q;
    return v ^ (((v >> cc) & 1u) << tt);
}
static unsigned C1(unsigned v)  { for (int q = 0;      q < NQ; ++q) v = Pp(v, q); return v; }
static unsigned C1i(unsigned v) { for (int q = NQ - 1; q >= 0; --q) v = Pp(v, q); return v; }

extern "C" void kernel_launch(void* const* d_in, const int* in_sizes, int n_in,
                              void* d_out, int out_size)
{
    SetupCfg sc; MainCfg mc;
    memset(&sc, 0, sizeof(sc));
    memset(&mc, 0, sizeof(mc));

    // Phase masks mu_{l,q} = row_{13-q}(M^l), M = C1's GF(2) matrix (tau = I frame).
    for (int l = 0; l < NL; ++l) {
        unsigned col[NQ];
        for (int j = 0; j < NQ; ++j) {
            unsigned v = 1u << j;
            for (int r = 0; r < l; ++r) v = C1(v);
            col[j] = v;
        }
        for (int q = 0; q < NQ; ++q) {
            unsigned mask = 0;
            for (int j = 0; j < NQ; ++j) mask |= ((col[j] >> (13 - q)) & 1u) << j;
            sc.mu[l * NQ + q] = (unsigned short)mask;
        }
    }

    int soff = 0, tcur = 0;
    for (int m = 0; m < NQ; ++m) {
        unsigned dl = 1u << m;
        for (int r = 0; r < NL; ++r) dl = C1i(dl);     // delta_m = M^-4 e_m (R7-validated colM)
        sc.delta[m] = (unsigned short)dl;
        int k = __builtin_popcount(dl);
        sc.k[m] = (unsigned char)k;
        int nd = 0, nc = 0;
        for (int bb = 0; bb < NQ; ++bb) {
            if ((dl >> bb) & 1) sc.dbits[m][nd++] = (unsigned char)bb;
            else                sc.cbits[m][nc++] = (unsigned char)bb;
        }
        int keff = k - 1;
        int klo  = keff < 6 ? keff : 6;
        mc.keff[m] = (unsigned char)keff;
        mc.klo[m]  = (unsigned char)klo;
        mc.khi[m]  = (unsigned char)(keff - klo);
        mc.jtop[m] = sc.dbits[m][k - 1];
        for (int r = 0; r < keff; ++r) mc.jb[m][r] = sc.dbits[m][r];
        sc.soff[m] = mc.soff[m] = soff;
        soff += 1 << keff;
        mc.ploff[m] = tcur; tcur += 1 << klo;
        mc.phoff[m] = tcur; tcur += 1 << (keff - klo);
    }
    mc.s_total = soff;
    mc.t_total = tcur;
    mc.stage   = (soff <= SCAP) ? 1 : 0;

    const float* x      = (const float*)d_in[0];
    const float* params = (const float*)d_in[1];
    const int    batch  = in_sizes[0] / NQ;

    qsetup<<<dim3(NQ, SBLK), STH>>>(params, sc);

    const int smem = ((mc.stage ? mc.s_total : 0) + mc.t_total) * (int)sizeof(float2);
    cudaFuncSetAttribute(qmain, cudaFuncAttributeMaxDynamicSharedMemorySize, smem);
    const int grid = (batch + MB - 1) / MB;
    qmain<<<grid, MTH, smem>>>(x, (float*)d_out, batch, mc);
}

// round 11
// speedup vs baseline: 2.8489x; 2.8489x over previous
#include <cuda_runtime.h>
#include <string.h>
#include <math.h>

#define NQ 14
#define NL 4
#define NGATES 56
#define MB 4

// Param-only bucket tables S_m(t); worst case 14*8192 entries.
__device__ float2 g_S[14 * 8192];

struct SetupCfg {
    unsigned short mu[NGATES];          // phase parity masks (rows of M^l)
    unsigned long long glmask[NQ];      // gates with odd intersection vs delta_m
    unsigned char  k[NQ];               // popc(delta_m)
    unsigned char  dbits[NQ][NQ];       // delta bits ascending
    unsigned char  cbits[NQ][NQ];       // complement bits ascending
    int soff[NQ];
};

struct MainCfg {
    unsigned char keff[NQ], klo[NQ], khi[NQ], jtop[NQ];
    unsigned char jb[NQ][NQ];
    int soff[NQ], ploff[NQ], phoff[NQ];
    int t_total;
};

__device__ __forceinline__ float2 cmulf(float2 a, float2 b) {
    return make_float2(a.x * b.x - a.y * b.y, a.x * b.y + a.y * b.x);
}

__global__ void __launch_bounds__(256)
qzero(int n)
{
    int i = blockIdx.x * 256 + threadIdx.x;
    if (i < n) g_S[i] = make_float2(0.f, 0.f);
}

// One thread per (t, f) pair: 8192 pairs per qubit m. grid = (32, NQ), block = 256.
__global__ void __launch_bounds__(256)
qsetup(const float* __restrict__ params, SetupCfg c)
{
    __shared__ float th[NGATES];
    __shared__ unsigned short mus[NGATES];
    __shared__ float2 part[8];

    const int m = blockIdx.y, tid = threadIdx.x;
    if (tid < NGATES) { th[tid] = params[tid]; mus[tid] = c.mu[tid]; }
    __syncthreads();

    const int k    = c.k[m];
    const int nfl  = 14 - k;            // log2(free values per bucket)
    const int keff = k - 1;
    const int nf   = 1 << nfl;
    const int pair = blockIdx.x * 256 + tid;
    const int t    = pair >> nfl;
    const int f    = pair & (nf - 1);

    unsigned p = 0;
    for (int r = 0; r < keff; ++r) p |= ((unsigned)(t >> r) & 1u) << c.dbits[m][r];
    for (int r = 0; r < nfl;  ++r) p |= ((unsigned)(f >> r) & 1u) << c.cbits[m][r];

    const unsigned long long gm = c.glmask[m];
    float ang = 0.f;
    #pragma unroll
    for (int g = 0; g < NGATES; ++g) {
        if ((gm >> g) & 1ull)
            ang += (__popc(p & (unsigned)mus[g]) & 1) ? -th[g] : th[g];
    }
    float2 v;
    sincosf(ang, &v.y, &v.x);

    // segmented reduction over the f-run
    const int wl = nf < 32 ? nf : 32;
    for (int o = 1; o < wl; o <<= 1) {
        v.x += __shfl_xor_sync(0xffffffffu, v.x, o);
        v.y += __shfl_xor_sync(0xffffffffu, v.y, o);
    }
    if (nf <= 32) {
        if ((f & (nf - 1)) == 0) g_S[c.soff[m] + t] = v;
    } else {
        if ((tid & 31) == 0) part[tid >> 5] = v;
        __syncthreads();
        if (nf <= 256) {
            const int bpb = 256 / nf, wps = nf / 32;
            if (tid < bpb) {
                float2 s = make_float2(0.f, 0.f);
                for (int w = 0; w < wps; ++w) {
                    s.x += part[tid * wps + w].x;
                    s.y += part[tid * wps + w].y;
                }
                g_S[c.soff[m] + ((blockIdx.x * 256) >> nfl) + tid] = s;
            }
        } else {
            if (tid == 0) {
                float2 s = make_float2(0.f, 0.f);
                for (int w = 0; w < 8; ++w) { s.x += part[w].x; s.y += part[w].y; }
                atomicAdd(&g_S[c.soff[m] + t].x, s.x);
                atomicAdd(&g_S[c.soff[m] + t].y, s.y);
            }
        }
    }
}

// One block per MB batch elements; S read through L1 (fits: <=64KB).
__global__ void __launch_bounds__(256)
qmain(const float* __restrict__ x, float* __restrict__ out, int batch, MainCfg c)
{
    extern __shared__ float2 T[];
    __shared__ float2 u[NQ];
    __shared__ float red[8][NQ];
    const int tid = threadIdx.x;

    #pragma unroll 1
    for (int bi = 0; bi < MB; ++bi) {
        const int b = blockIdx.x * MB + bi;
        if (b >= batch) break;

        if (tid < NQ) {   // u[j] = e^{i x_{13-j}}, j = storage bit
            float s, co;
            sincosf(x[b * NQ + 13 - tid], &s, &co);
            u[tid] = make_float2(co, s);
        }
        __syncthreads();

        // split phasor tables PL/PH for all m
        #pragma unroll 1
        for (int m = 0; m < NQ; ++m) {
            const int klo = c.klo[m], khi = c.khi[m];
            for (int e = tid; e < (1 << klo); e += 256) {
                float2 v = make_float2(1.f, 0.f);
                for (int r = 0; r < klo; ++r) {
                    float2 w = u[c.jb[m][r]];
                    if ((e >> r) & 1) w.y = -w.y;
                    v = cmulf(v, w);
                }
                T[c.ploff[m] + e] = v;
            }
            for (int e = tid; e < (1 << khi); e += 256) {
                float2 v = u[c.jtop[m]];   // fixed top bit (=0) contributes +x_{jtop}
                for (int r = 0; r < khi; ++r) {
                    float2 w = u[c.jb[m][klo + r]];
                    if ((e >> r) & 1) w.y = -w.y;
                    v = cmulf(v, w);
                }
                T[c.phoff[m] + e] = v;
            }
        }
        __syncthreads();

        float a14[NQ];
        #pragma unroll 1
        for (int m = 0; m < NQ; ++m) {
            const int nt = 1 << c.keff[m], klo = c.klo[m];
            const int so = c.soff[m];
            const float2  pl  = T[c.ploff[m] + (tid & ((1 << klo) - 1))];
            const float2* Tph = T + c.phoff[m];
            float a = 0.f;
            for (int t = tid; t < nt; t += 256) {
                float2 P = cmulf(pl, Tph[t >> klo]);
                float2 S = __ldg(&g_S[so + t]);
                a = fmaf(P.x, S.x, a);
                a = fmaf(-P.y, S.y, a);
            }
            a14[m] = a;
        }

        #pragma unroll
        for (int m = 0; m < NQ; ++m)
            #pragma unroll
            for (int o = 16; o; o >>= 1)
                a14[m] += __shfl_down_sync(0xffffffffu, a14[m], o);
        if ((tid & 31) == 0)
            for (int m = 0; m < NQ; ++m) red[tid >> 5][m] = a14[m];
        __syncthreads();
        if (tid < NQ) {
            float tot = 0.f;
            #pragma unroll
            for (int w = 0; w < 8; ++w) tot += red[w][13 - tid];
            out[b * NQ + tid] = tot * (1.f / 8192.f);   // 2 / 2^14
        }
        __syncthreads();
    }
}

// ================= host side (mask math identical to validated R8) =================
static unsigned Pp(unsigned v, int q) {
    int cc = 13 - ((q + 1) % NQ);
    int tt = 13 - q;
    return v ^ (((v >> cc) & 1u) << tt);
}
static unsigned C1(unsigned v)  { for (int q = 0;      q < NQ; ++q) v = Pp(v, q); return v; }
static unsigned C1i(unsigned v) { for (int q = NQ - 1; q >= 0; --q) v = Pp(v, q); return v; }

extern "C" void kernel_launch(void* const* d_in, const int* in_sizes, int n_in,
                              void* d_out, int out_size)
{
    SetupCfg sc; MainCfg mc;
    memset(&sc, 0, sizeof(sc));
    memset(&mc, 0, sizeof(mc));

    for (int l = 0; l < NL; ++l) {
        unsigned col[NQ];
        for (int j = 0; j < NQ; ++j) {
            unsigned v = 1u << j;
            for (int r = 0; r < l; ++r) v = C1(v);
            col[j] = v;
        }
        for (int q = 0; q < NQ; ++q) {
            unsigned mask = 0;
            for (int j = 0; j < NQ; ++j) mask |= ((col[j] >> (13 - q)) & 1u) << j;
            sc.mu[l * NQ + q] = (unsigned short)mask;
        }
    }

    int soff = 0, tcur = 0;
    for (int m = 0; m < NQ; ++m) {
        unsigned dl = 1u << m;
        for (int r = 0; r < NL; ++r) dl = C1i(dl);
        int k = __builtin_popcount(dl);
        sc.k[m] = (unsigned char)k;
        unsigned long long gm = 0;
        for (int g = 0; g < NGATES; ++g)
            if (__builtin_popcount((unsigned)sc.mu[g] & dl) & 1) gm |= 1ull << g;
        sc.glmask[m] = gm;
        int nd = 0, nc = 0;
        for (int bb = 0; bb < NQ; ++bb) {
            if ((dl >> bb) & 1) sc.dbits[m][nd++] = (unsigned char)bb;
            else                sc.cbits[m][nc++] = (unsigned char)bb;
        }
        int keff = k - 1;
        int klo  = keff < 6 ? keff : 6;
        mc.keff[m] = (unsigned char)keff;
        mc.klo[m]  = (unsigned char)klo;
        mc.khi[m]  = (unsigned char)(keff - klo);
        mc.jtop[m] = sc.dbits[m][k - 1];
        for (int r = 0; r < keff; ++r) mc.jb[m][r] = sc.dbits[m][r];
        sc.soff[m] = mc.soff[m] = soff;
        soff += 1 << keff;
        mc.ploff[m] = tcur; tcur += 1 << klo;
        mc.phoff[m] = tcur; tcur += 1 << (keff - klo);
    }
    mc.t_total = tcur;

    const float* x      = (const float*)d_in[0];
    const float* params = (const float*)d_in[1];
    const int    batch  = in_sizes[0] / NQ;

    qzero<<<(soff + 255) / 256, 256>>>(soff);
    qsetup<<<dim3(32, NQ), 256>>>(params, sc);

    const int smem = mc.t_total * (int)sizeof(float2);
    cudaFuncSetAttribute(qmain, cudaFuncAttributeMaxDynamicSharedMemorySize, smem);
    qmain<<<(batch + MB - 1) / MB, 256, smem>>>(x, (float*)d_out, batch, mc);
}

// round 13
// speedup vs baseline: 5.0976x; 1.7893x over previous
#include <cuda_runtime.h>
#include <string.h>
#include <math.h>

#define NQ 14
#define NL 4
#define NGATES 56
#define MB 4

// Param-only bucket tables S_m(t).
__device__ float2 g_S[14 * 8192];

struct SetupCfg {
    unsigned long long WA[NQ][128];   // signword of pair low-7 bits (GF2-linear)
    unsigned long long WB[NQ][64];    // signword of pair high-6 bits
    unsigned char gl[NQ][56];         // G_m gate list, 0xFF pad (chunked by 7)
    unsigned char vmask[NQ][8];       // valid-slot mask per chunk
    unsigned char nch[NQ];
    unsigned char nfl[NQ];            // 14 - k
    int soff[NQ];
};

struct MainCfg {
    unsigned char keff[NQ], klo[NQ], khi[NQ], jtop[NQ];
    unsigned char jb[NQ][NQ];
    int soff[NQ], ploff[NQ], phoff[NQ];
    int t_total;
};

__device__ __forceinline__ float2 cmulf(float2 a, float2 b) {
    return make_float2(a.x * b.x - a.y * b.y, a.x * b.y + a.y * b.x);
}

__global__ void __launch_bounds__(256)
qzero(int n)
{
    int i = blockIdx.x * 256 + threadIdx.x;
    if (i < n) g_S[i] = make_float2(0.f, 0.f);
}

// grid (32, NQ), block 256: one thread per (t, f) pair (8192 per qubit).
__global__ void __launch_bounds__(256)
qsetup(const float* __restrict__ params, SetupCfg c)
{
    __shared__ unsigned long long WA[128], WB[64];
    __shared__ float TD[8 * 128];
    __shared__ float th[NGATES];
    __shared__ float thetaTot;
    __shared__ float2 part[8];

    const int m = blockIdx.y, tid = threadIdx.x;
    if (tid < NGATES) th[tid] = params[tid];
    if (tid < 128) WA[tid] = c.WA[m][tid];
    if (tid >= 128 && tid < 192) WB[tid - 128] = c.WB[m][tid - 128];
    __syncthreads();

    // TD[c][idx] = sum of theta over set idx-bits of chunk c
    for (int e = tid; e < 1024; e += 256) {
        const int ch = e >> 7, idx = e & 127;
        float s = 0.f;
        #pragma unroll
        for (int r = 0; r < 7; ++r) {
            unsigned char g = c.gl[m][ch * 7 + r];
            if (((idx >> r) & 1) && g != 0xFF) s += th[g];
        }
        TD[e] = s;
    }
    __syncthreads();
    if (tid == 0) {
        float s = 0.f;
        for (int ch = 0; ch < c.nch[m]; ++ch) s += TD[ch * 128 + c.vmask[m][ch]];
        thetaTot = s;
    }
    __syncthreads();

    const int nfl = c.nfl[m], nf = 1 << nfl;
    const int pair = blockIdx.x * 256 + tid;
    unsigned long long w = WA[pair & 127] ^ WB[pair >> 7];
    float dot = 0.f;
    const int nch = c.nch[m];
    for (int ch = 0; ch < nch; ++ch)
        dot += TD[ch * 128 + (int)((w >> (7 * ch)) & 127ull)];
    const float ang = thetaTot - 2.f * dot;
    float2 v;
    sincosf(ang, &v.y, &v.x);

    // segmented reduction over the f-run (f = low nfl bits of pair)
    const int f  = tid & (nf - 1);
    const int wl = nf < 32 ? nf : 32;
    for (int o = 1; o < wl; o <<= 1) {
        v.x += __shfl_xor_sync(0xffffffffu, v.x, o);
        v.y += __shfl_xor_sync(0xffffffffu, v.y, o);
    }
    if (nf <= 32) {
        if (f == 0) g_S[c.soff[m] + (pair >> nfl)] = v;
    } else {
        if ((tid & 31) == 0) part[tid >> 5] = v;
        __syncthreads();
        if (nf <= 256) {
            const int bpb = 256 / nf, wps = nf / 32;
            if (tid < bpb) {
                float2 s = make_float2(0.f, 0.f);
                for (int ww = 0; ww < wps; ++ww) {
                    s.x += part[tid * wps + ww].x;
                    s.y += part[tid * wps + ww].y;
                }
                g_S[c.soff[m] + ((blockIdx.x * 256) >> nfl) + tid] = s;
            }
        } else {
            if (tid == 0) {
                float2 s = make_float2(0.f, 0.f);
                for (int ww = 0; ww < 8; ++ww) { s.x += part[ww].x; s.y += part[ww].y; }
                atomicAdd(&g_S[c.soff[m] + ((blockIdx.x * 256) >> nfl)].x, s.x);
                atomicAdd(&g_S[c.soff[m] + ((blockIdx.x * 256) >> nfl)].y, s.y);
            }
        }
    }
}

// One block per MB batch elements; S loads shared across the MB group.
__global__ void __launch_bounds__(256)
qmain(const float* __restrict__ x, float* __restrict__ out, int batch, MainCfg c)
{
    extern __shared__ float2 T[];            // batch-interleaved PL/PH tables
    __shared__ float2 u[MB][NQ];
    __shared__ float red[8][NQ][MB];
    const int tid = threadIdx.x;
    const int bbase = blockIdx.x * MB;

    if (tid < MB * NQ) {
        int b = tid / NQ, j = tid % NQ;
        int bb = bbase + b; if (bb >= batch) bb = batch - 1;
        float s, co;
        sincosf(x[bb * NQ + (13 - j)], &s, &co);   // u[j] = e^{i x_{13-j}}
        u[b][j] = make_float2(co, s);
    }
    __syncthreads();

    // build tables: entry i = e*MB + b
    #pragma unroll 1
    for (int m = 0; m < NQ; ++m) {
        const int klo = c.klo[m], khi = c.khi[m];
        const int npl = (1 << klo) * MB, nph = (1 << khi) * MB;
        for (int i = tid; i < npl; i += 256) {
            const int b = i & (MB - 1), e = i >> 2;
            float2 v = make_float2(1.f, 0.f);
            for (int r = 0; r < klo; ++r) {
                float2 wv = u[b][c.jb[m][r]];
                if ((e >> r) & 1) wv.y = -wv.y;
                v = cmulf(v, wv);
            }
            T[c.ploff[m] + i] = v;
        }
        for (int i = tid; i < nph; i += 256) {
            const int b = i & (MB - 1), e = i >> 2;
            float2 v = u[b][c.jtop[m]];        // fixed top delta bit contributes +x
            for (int r = 0; r < khi; ++r) {
                float2 wv = u[b][c.jb[m][klo + r]];
                if ((e >> r) & 1) wv.y = -wv.y;
                v = cmulf(v, wv);
            }
            T[c.phoff[m] + i] = v;
        }
    }
    __syncthreads();

    const int warp = tid >> 5, lane = tid & 31;
    #pragma unroll 1
    for (int m = 0; m < NQ; ++m) {
        const int klo = c.klo[m];
        const int nt  = 1 << c.keff[m];
        const float2* __restrict__ Tph = T + c.phoff[m];
        const int so = c.soff[m];
        float ax0 = 0.f, ay0 = 0.f, ax1 = 0.f, ay1 = 0.f;
        float ax2 = 0.f, ay2 = 0.f, ax3 = 0.f, ay3 = 0.f;
        for (int t = tid; t < nt; t += 256) {
            const float2 S = __ldg(&g_S[so + t]);
            const int th_ = (t >> klo) * MB;   // warp-uniform for klo>=5
            const float2 p0 = Tph[th_ + 0], p1 = Tph[th_ + 1];
            const float2 p2 = Tph[th_ + 2], p3 = Tph[th_ + 3];
            ax0 = fmaf(p0.x, S.x, ax0); ax0 = fmaf(-p0.y, S.y, ax0);
            ay0 = fmaf(p0.x, S.y, ay0); ay0 = fmaf( p0.y, S.x, ay0);
            ax1 = fmaf(p1.x, S.x, ax1); ax1 = fmaf(-p1.y, S.y, ax1);
            ay1 = fmaf(p1.x, S.y, ay1); ay1 = fmaf( p1.y, S.x, ay1);
            ax2 = fmaf(p2.x, S.x, ax2); ax2 = fmaf(-p2.y, S.y, ax2);
            ay2 = fmaf(p2.x, S.y, ay2); ay2 = fmaf( p2.y, S.x, ay2);
            ax3 = fmaf(p3.x, S.x, ax3); ax3 = fmaf(-p3.y, S.y, ax3);
            ay3 = fmaf(p3.x, S.y, ay3); ay3 = fmaf( p3.y, S.x, ay3);
        }
        const int tl = tid & ((1 << klo) - 1);
        const float2* Tpl = T + c.ploff[m] + tl * MB;
        float r0 = Tpl[0].x * ax0 - Tpl[0].y * ay0;
        float r1 = Tpl[1].x * ax1 - Tpl[1].y * ay1;
        float r2 = Tpl[2].x * ax2 - Tpl[2].y * ay2;
        float r3 = Tpl[3].x * ax3 - Tpl[3].y * ay3;
        #pragma unroll
        for (int o = 16; o; o >>= 1) {
            r0 += __shfl_down_sync(0xffffffffu, r0, o);
            r1 += __shfl_down_sync(0xffffffffu, r1, o);
            r2 += __shfl_down_sync(0xffffffffu, r2, o);
            r3 += __shfl_down_sync(0xffffffffu, r3, o);
        }
        if (lane == 0) {
            red[warp][m][0] = r0; red[warp][m][1] = r1;
            red[warp][m][2] = r2; red[warp][m][3] = r3;
        }
    }
    __syncthreads();
    if (tid < NQ * MB) {
        const int m = tid >> 2, b = tid & 3;
        float s = 0.f;
        #pragma unroll
        for (int w2 = 0; w2 < 8; ++w2) s += red[w2][m][b];
        const int bb = bbase + b;
        if (bb < batch) out[bb * NQ + (13 - m)] = s * (1.f / 8192.f);
    }
}

// ================= host side (mask math identical to validated R8/R9) =================
static unsigned Pp(unsigned v, int q) {
    int cc = 13 - ((q + 1) % NQ);
    int tt = 13 - q;
    return v ^ (((v >> cc) & 1u) << tt);
}
static unsigned C1(unsigned v)  { for (int q = 0;      q < NQ; ++q) v = Pp(v, q); return v; }
static unsigned C1i(unsigned v) { for (int q = NQ - 1; q >= 0; --q) v = Pp(v, q); return v; }

extern "C" void kernel_launch(void* const* d_in, const int* in_sizes, int n_in,
                              void* d_out, int out_size)
{
    static SetupCfg sc;   // large; static avoids stack issues (host-side only)
    static MainCfg  mc;
    memset(&sc, 0, sizeof(sc));
    memset(&mc, 0, sizeof(mc));

    unsigned mu[NGATES];
    for (int l = 0; l < NL; ++l) {
        unsigned col[NQ];
        for (int j = 0; j < NQ; ++j) {
            unsigned v = 1u << j;
            for (int r = 0; r < l; ++r) v = C1(v);
            col[j] = v;
        }
        for (int q = 0; q < NQ; ++q) {
            unsigned mask = 0;
            for (int j = 0; j < NQ; ++j) mask |= ((col[j] >> (13 - q)) & 1u) << j;
            mu[l * NQ + q] = mask;
        }
    }

    int soff = 0, tcur = 0, need_zero = 0;
    for (int m = 0; m < NQ; ++m) {
        unsigned dl = 1u << m;
        for (int r = 0; r < NL; ++r) dl = C1i(dl);
        const int k = __builtin_popcount(dl);
        unsigned char dbits[NQ], cbits[NQ];
        int nd = 0, nc2 = 0;
        for (int bb = 0; bb < NQ; ++bb) {
            if ((dl >> bb) & 1) dbits[nd++] = (unsigned char)bb;
            else                cbits[nc2++] = (unsigned char)bb;
        }
        // G_m gate list
        int ngl = 0;
        unsigned char glist[NGATES];
        for (int g = 0; g < NGATES; ++g)
            if (__builtin_popcount(mu[g] & dl) & 1) glist[ngl++] = (unsigned char)g;
        memset(sc.gl[m], 0xFF, 56);
        for (int r = 0; r < ngl; ++r) sc.gl[m][r] = glist[r];
        const int nch = (ngl + 6) / 7;
        sc.nch[m] = (unsigned char)nch;
        for (int ch = 0; ch < nch; ++ch) {
            int nv = ngl - 7 * ch; if (nv > 7) nv = 7;
            sc.vmask[m][ch] = (unsigned char)((1 << nv) - 1);
        }
        const int keff = k - 1, nfl = 14 - k;
        sc.nfl[m] = (unsigned char)nfl;
        if (nfl > 8) need_zero = 1;
        // signword tables over pair bits (pair: low nfl bits=f->cbits, next keff bits=t->dbits)
        auto pair2p = [&](unsigned pr) {
            unsigned p = 0;
            for (int r = 0; r < nfl;  ++r) if ((pr >> r) & 1)         p |= 1u << cbits[r];
            for (int r = 0; r < keff; ++r) if ((pr >> (nfl + r)) & 1) p |= 1u << dbits[r];
            return p;
        };
        auto sigw = [&](unsigned p) {
            unsigned long long w = 0;
            for (int r = 0; r < ngl; ++r)
                if (__builtin_popcount(p & mu[glist[r]]) & 1) w |= 1ull << r;
            return w;
        };
        for (int a = 0; a < 128; ++a) sc.WA[m][a] = sigw(pair2p((unsigned)a));
        for (int h = 0; h < 64;  ++h) sc.WB[m][h] = sigw(pair2p(((unsigned)h) << 7));

        // main cfg
        int klo = keff - 4; if (klo < 5) klo = 5; if (klo > keff) klo = keff; if (klo > 8) klo = 8;
        mc.keff[m] = (unsigned char)keff;
        mc.klo[m]  = (unsigned char)klo;
        mc.khi[m]  = (unsigned char)(keff - klo);
        mc.jtop[m] = dbits[k - 1];
        for (int r = 0; r < keff; ++r) mc.jb[m][r] = dbits[r];
        sc.soff[m] = mc.soff[m] = soff;
        soff += 1 << keff;
        mc.ploff[m] = tcur; tcur += (1 << klo) * MB;
        mc.phoff[m] = tcur; tcur += (1 << (keff - klo)) * MB;
    }
    mc.t_total = tcur;

    const float* x      = (const float*)d_in[0];
    const float* params = (const float*)d_in[1];
    const int    batch  = in_sizes[0] / NQ;

    if (need_zero) qzero<<<(soff + 255) / 256, 256>>>(soff);
    qsetup<<<dim3(32, NQ), 256>>>(params, sc);

    const int smem = mc.t_total * (int)sizeof(float2);
    cudaFuncSetAttribute(qmain, cudaFuncAttributeMaxDynamicSharedMemorySize, smem);
    qmain<<<(batch + MB - 1) / MB, 256, smem>>>(x, (float*)d_out, batch, mc);
}

// round 15
// speedup vs baseline: 6.4655x; 1.2683x over previous
#include <cuda_runtime.h>
#include <string.h>
#include <math.h>

#define NQ 14
#define NL 4
#define NGATES 56
#define MB 4

// Param-only bucket tables S_m(t).
__device__ float2 g_S[14 * 8192];

struct SetupCfg {
    unsigned long long WA[NQ][128];   // signword of pair low-7 bits (GF2-linear)
    unsigned long long WB[NQ][64];    // signword of pair high-6 bits
    unsigned char gl[NQ][56];         // G_m gate list, 0xFF pad (chunked by 7)
    unsigned char vmask[NQ][8];       // valid-slot mask per chunk
    unsigned char nch[NQ];
    unsigned char nfl[NQ];            // 14 - k
    int soff[NQ];
};

struct MainCfg {
    unsigned char keff[NQ], klo[NQ], khi[NQ], jtop[NQ];
    unsigned char jb[NQ][NQ];
    int soff[NQ];
};

__device__ __forceinline__ float2 cmulf(float2 a, float2 b) {
    return make_float2(a.x * b.x - a.y * b.y, a.x * b.y + a.y * b.x);
}

__global__ void __launch_bounds__(256)
qzero(int n)
{
    int i = blockIdx.x * 256 + threadIdx.x;
    if (i < n) g_S[i] = make_float2(0.f, 0.f);
}

// grid (32, NQ), block 256: one thread per (t, f) pair (8192 per qubit). Validated R12.
__global__ void __launch_bounds__(256)
qsetup(const float* __restrict__ params, SetupCfg c)
{
    __shared__ unsigned long long WA[128], WB[64];
    __shared__ float TD[8 * 128];
    __shared__ float th[NGATES];
    __shared__ float thetaTot;
    __shared__ float2 part[8];

    const int m = blockIdx.y, tid = threadIdx.x;
    if (tid < NGATES) th[tid] = params[tid];
    if (tid < 128) WA[tid] = c.WA[m][tid];
    if (tid >= 128 && tid < 192) WB[tid - 128] = c.WB[m][tid - 128];
    __syncthreads();

    for (int e = tid; e < 1024; e += 256) {
        const int ch = e >> 7, idx = e & 127;
        float s = 0.f;
        #pragma unroll
        for (int r = 0; r < 7; ++r) {
            unsigned char g = c.gl[m][ch * 7 + r];
            if (((idx >> r) & 1) && g != 0xFF) s += th[g];
        }
        TD[e] = s;
    }
    __syncthreads();
    if (tid == 0) {
        float s = 0.f;
        for (int ch = 0; ch < c.nch[m]; ++ch) s += TD[ch * 128 + c.vmask[m][ch]];
        thetaTot = s;
    }
    __syncthreads();

    const int nfl = c.nfl[m], nf = 1 << nfl;
    const int pair = blockIdx.x * 256 + tid;
    unsigned long long w = WA[pair & 127] ^ WB[pair >> 7];
    float dot = 0.f;
    const int nch = c.nch[m];
    for (int ch = 0; ch < nch; ++ch)
        dot += TD[ch * 128 + (int)((w >> (7 * ch)) & 127ull)];
    const float ang = thetaTot - 2.f * dot;
    float2 v;
    sincosf(ang, &v.y, &v.x);

    const int f  = tid & (nf - 1);
    const int wl = nf < 32 ? nf : 32;
    for (int o = 1; o < wl; o <<= 1) {
        v.x += __shfl_xor_sync(0xffffffffu, v.x, o);
        v.y += __shfl_xor_sync(0xffffffffu, v.y, o);
    }
    if (nf <= 32) {
        if (f == 0) g_S[c.soff[m] + (pair >> nfl)] = v;
    } else {
        if ((tid & 31) == 0) part[tid >> 5] = v;
        __syncthreads();
        if (nf <= 256) {
            const int bpb = 256 / nf, wps = nf / 32;
            if (tid < bpb) {
                float2 s = make_float2(0.f, 0.f);
                for (int ww = 0; ww < wps; ++ww) {
                    s.x += part[tid * wps + ww].x;
                    s.y += part[tid * wps + ww].y;
                }
                g_S[c.soff[m] + ((blockIdx.x * 256) >> nfl) + tid] = s;
            }
        } else {
            if (tid == 0) {
                float2 s = make_float2(0.f, 0.f);
                for (int ww = 0; ww < 8; ++ww) { s.x += part[ww].x; s.y += part[ww].y; }
                atomicAdd(&g_S[c.soff[m] + ((blockIdx.x * 256) >> nfl)].x, s.x);
                atomicAdd(&g_S[c.soff[m] + ((blockIdx.x * 256) >> nfl)].y, s.y);
            }
        }
    }
}

// One block per MB batch elements. PL = PA*PB in registers; PH tiny uniform table.
__global__ void __launch_bounds__(256)
qmain(const float* __restrict__ x, float* __restrict__ out, int batch, MainCfg c)
{
    __shared__ float2 u[MB][NQ];
    __shared__ float4 PA[NQ][16][2];   // [m][e][half]: 4 batch float2 per entry
    __shared__ float4 PB[NQ][16][2];
    __shared__ float4 PH[NQ][8][2];
    __shared__ float red[8][NQ][MB];

    const int tid = threadIdx.x;
    const int bbase = blockIdx.x * MB;

    if (tid < MB * NQ) {
        int b = tid / NQ, j = tid % NQ;
        int bb = bbase + b; if (bb >= batch) bb = batch - 1;
        float s, co;
        sincosf(x[bb * NQ + (13 - j)], &s, &co);   // u[j] = e^{i x_{13-j}}
        u[b][j] = make_float2(co, s);
    }
    __syncthreads();

    // fused build of all PA/PB/PH entries: 14 * (64+64+32) = 2240 slots
    for (int E = tid; E < NQ * 160; E += 256) {
        const int m = E / 160, s = E - m * 160;
        const int klo = c.klo[m];
        float2 v;
        float2* dst;
        if (s < 64) {
            const int e = s >> 2, b = s & 3;
            v = make_float2(1.f, 0.f);
            const int nb = klo < 4 ? klo : 4;
            for (int r = 0; r < nb; ++r) {
                float2 w = u[b][c.jb[m][r]];
                if ((e >> r) & 1) w.y = -w.y;
                v = cmulf(v, w);
            }
            dst = reinterpret_cast<float2*>(&PA[m][e][0]) + b;
        } else if (s < 128) {
            const int e = (s - 64) >> 2, b = (s - 64) & 3;
            v = make_float2(1.f, 0.f);
            const int nb = klo > 4 ? klo - 4 : 0;
            for (int r = 0; r < nb; ++r) {
                float2 w = u[b][c.jb[m][4 + r]];
                if ((e >> r) & 1) w.y = -w.y;
                v = cmulf(v, w);
            }
            dst = reinterpret_cast<float2*>(&PB[m][e][0]) + b;
        } else {
            const int e = (s - 128) >> 2, b = (s - 128) & 3;
            v = u[b][c.jtop[m]];          // fixed top delta bit contributes +x
            const int nb = c.khi[m];
            for (int r = 0; r < nb; ++r) {
                float2 w = u[b][c.jb[m][klo + r]];
                if ((e >> r) & 1) w.y = -w.y;
                v = cmulf(v, w);
            }
            dst = reinterpret_cast<float2*>(&PH[m][e][0]) + b;
        }
        *dst = v;
    }
    __syncthreads();

    const int warp = tid >> 5, lane = tid & 31;
    #pragma unroll 1
    for (int m = 0; m < NQ; ++m) {
        const int klo = c.klo[m];
        const int lomask = (1 << klo) - 1;
        const int nt = 1 << c.keff[m];
        const int so = c.soff[m];

        // per-thread PL = PA[eA] * PB[eB] (registers)
        const float4 a0 = PA[m][tid & 15][0],            a1 = PA[m][tid & 15][1];
        const float4 b0 = PB[m][(tid & lomask) >> 4][0], b1 = PB[m][(tid & lomask) >> 4][1];
        const float2 pl0 = cmulf(make_float2(a0.x, a0.y), make_float2(b0.x, b0.y));
        const float2 pl1 = cmulf(make_float2(a0.z, a0.w), make_float2(b0.z, b0.w));
        const float2 pl2 = cmulf(make_float2(a1.x, a1.y), make_float2(b1.x, b1.y));
        const float2 pl3 = cmulf(make_float2(a1.z, a1.w), make_float2(b1.z, b1.w));

        float ax0 = 0.f, ay0 = 0.f, ax1 = 0.f, ay1 = 0.f;
        float ax2 = 0.f, ay2 = 0.f, ax3 = 0.f, ay3 = 0.f;
        for (int t = tid; t < nt; t += 256) {
            const float2 S = __ldg(&g_S[so + t]);
            const float4 h0 = PH[m][t >> klo][0];   // warp-uniform broadcast
            const float4 h1 = PH[m][t >> klo][1];
            ax0 = fmaf(h0.x, S.x, ax0); ax0 = fmaf(-h0.y, S.y, ax0);
            ay0 = fmaf(h0.x, S.y, ay0); ay0 = fmaf( h0.y, S.x, ay0);
            ax1 = fmaf(h0.z, S.x, ax1); ax1 = fmaf(-h0.w, S.y, ax1);
            ay1 = fmaf(h0.z, S.y, ay1); ay1 = fmaf( h0.w, S.x, ay1);
            ax2 = fmaf(h1.x, S.x, ax2); ax2 = fmaf(-h1.y, S.y, ax2);
            ay2 = fmaf(h1.x, S.y, ay2); ay2 = fmaf( h1.y, S.x, ay2);
            ax3 = fmaf(h1.z, S.x, ax3); ax3 = fmaf(-h1.w, S.y, ax3);
            ay3 = fmaf(h1.z, S.y, ay3); ay3 = fmaf( h1.w, S.x, ay3);
        }
        float r0 = pl0.x * ax0 - pl0.y * ay0;
        float r1 = pl1.x * ax1 - pl1.y * ay1;
        float r2 = pl2.x * ax2 - pl2.y * ay2;
        float r3 = pl3.x * ax3 - pl3.y * ay3;
        #pragma unroll
        for (int o = 16; o; o >>= 1) {
            r0 += __shfl_down_sync(0xffffffffu, r0, o);
            r1 += __shfl_down_sync(0xffffffffu, r1, o);
            r2 += __shfl_down_sync(0xffffffffu, r2, o);
            r3 += __shfl_down_sync(0xffffffffu, r3, o);
        }
        if (lane == 0) {
            red[warp][m][0] = r0; red[warp][m][1] = r1;
            red[warp][m][2] = r2; red[warp][m][3] = r3;
        }
    }
    __syncthreads();
    if (tid < NQ * MB) {
        const int m = tid >> 2, b = tid & 3;
        float s = 0.f;
        #pragma unroll
        for (int w2 = 0; w2 < 8; ++w2) s += red[w2][m][b];
        const int bb = bbase + b;
        if (bb < batch) out[bb * NQ + (13 - m)] = s * (1.f / 8192.f);
    }
}

// ================= host side (mask math identical to validated R8-R12) =================
static unsigned Pp(unsigned v, int q) {
    int cc = 13 - ((q + 1) % NQ);
    int tt = 13 - q;
    return v ^ (((v >> cc) & 1u) << tt);
}
static unsigned C1(unsigned v)  { for (int q = 0;      q < NQ; ++q) v = Pp(v, q); return v; }
static unsigned C1i(unsigned v) { for (int q = NQ - 1; q >= 0; --q) v = Pp(v, q); return v; }

extern "C" void kernel_launch(void* const* d_in, const int* in_sizes, int n_in,
                              void* d_out, int out_size)
{
    static SetupCfg sc;
    static MainCfg  mc;
    memset(&sc, 0, sizeof(sc));
    memset(&mc, 0, sizeof(mc));

    unsigned mu[NGATES];
    for (int l = 0; l < NL; ++l) {
        unsigned col[NQ];
        for (int j = 0; j < NQ; ++j) {
            unsigned v = 1u << j;
            for (int r = 0; r < l; ++r) v = C1(v);
            col[j] = v;
        }
        for (int q = 0; q < NQ; ++q) {
            unsigned mask = 0;
            for (int j = 0; j < NQ; ++j) mask |= ((col[j] >> (13 - q)) & 1u) << j;
            mu[l * NQ + q] = mask;
        }
    }

    int soff = 0, need_zero = 0;
    for (int m = 0; m < NQ; ++m) {
        unsigned dl = 1u << m;
        for (int r = 0; r < NL; ++r) dl = C1i(dl);
        const int k = __builtin_popcount(dl);
        unsigned char dbits[NQ], cbits[NQ];
        int nd = 0, nc2 = 0;
        for (int bb = 0; bb < NQ; ++bb) {
            if ((dl >> bb) & 1) dbits[nd++] = (unsigned char)bb;
            else                cbits[nc2++] = (unsigned char)bb;
        }
        int ngl = 0;
        unsigned char glist[NGATES];
        for (int g = 0; g < NGATES; ++g)
            if (__builtin_popcount(mu[g] & dl) & 1) glist[ngl++] = (unsigned char)g;
        memset(sc.gl[m], 0xFF, 56);
        for (int r = 0; r < ngl; ++r) sc.gl[m][r] = glist[r];
        const int nch = (ngl + 6) / 7;
        sc.nch[m] = (unsigned char)nch;
        for (int ch = 0; ch < nch; ++ch) {
            int nv = ngl - 7 * ch; if (nv > 7) nv = 7;
            sc.vmask[m][ch] = (unsigned char)((1 << nv) - 1);
        }
        const int keff = k - 1, nfl = 14 - k;
        sc.nfl[m] = (unsigned char)nfl;
        if (nfl > 8) need_zero = 1;
        auto pair2p = [&](unsigned pr) {
            unsigned p = 0;
            for (int r = 0; r < nfl;  ++r) if ((pr >> r) & 1)         p |= 1u << cbits[r];
            for (int r = 0; r < keff; ++r) if ((pr >> (nfl + r)) & 1) p |= 1u << dbits[r];
            return p;
        };
        auto sigw = [&](unsigned p) {
            unsigned long long w = 0;
            for (int r = 0; r < ngl; ++r)
                if (__builtin_popcount(p & mu[glist[r]]) & 1) w |= 1ull << r;
            return w;
        };
        for (int a = 0; a < 128; ++a) sc.WA[m][a] = sigw(pair2p((unsigned)a));
        for (int h = 0; h < 64;  ++h) sc.WB[m][h] = sigw(pair2p(((unsigned)h) << 7));

        int klo = keff < 8 ? keff : 8;
        int khi = keff - klo;
        if (khi > 3) { klo = keff - 3; khi = 3; }   // PH table holds 8 entries
        mc.keff[m] = (unsigned char)keff;
        mc.klo[m]  = (unsigned char)klo;
        mc.khi[m]  = (unsigned char)khi;
        mc.jtop[m] = dbits[k - 1];
        for (int r = 0; r < keff; ++r) mc.jb[m][r] = dbits[r];
        sc.soff[m] = mc.soff[m] = soff;
        soff += 1 << keff;
    }

    const float* x      = (const float*)d_in[0];
    const float* params = (const float*)d_in[1];
    const int    batch  = in_sizes[0] / NQ;

    if (need_zero) qzero<<<(soff + 255) / 256, 256>>>(soff);
    qsetup<<<dim3(32, NQ), 256>>>(params, sc);
    qmain<<<(batch + MB - 1) / MB, 256>>>(x, (float*)d_out, batch, mc);
}